// round 2
// baseline (speedup 1.0000x reference)
#include <cuda_runtime.h>

#define D        128
#define NTEST    4096
#define NTRAIN   16384
#define TM       128
#define TN       128
#define MTILES   (NTEST / TM)       // 32
#define NCHUNKS  (NTRAIN / TN)      // 128
#define NJOBS    (MTILES * NCHUNKS) // 4096

// -------- scratch (device globals; no allocations allowed) --------
__device__ double g_colsum[D];
__device__ double g_colsumsq[D];
__device__ float  g_inv_bw[D];
__device__ float  g_Z;
__device__ float  g_tT[D * NTEST];    // scaled test, k-major: [k][m]
__device__ float  g_trT[D * NTRAIN];  // scaled train, k-major: [k][n]
__device__ float  g_tnorm[NTEST];
__device__ float  g_trnorm[NTRAIN];

// -------- f32x2 packed-FMA helpers (2x fp32 throughput on sm_103a) --------
typedef unsigned long long u64;
__device__ __forceinline__ u64 pk2(float lo, float hi) {
    u64 r; asm("mov.b64 %0, {%1,%2};" : "=l"(r) : "f"(lo), "f"(hi)); return r;
}
__device__ __forceinline__ void upk2(u64 v, float& lo, float& hi) {
    asm("mov.b64 {%0,%1}, %2;" : "=f"(lo), "=f"(hi) : "l"(v));
}
__device__ __forceinline__ u64 ffma2(u64 a, u64 b, u64 c) {
    u64 d; asm("fma.rn.f32x2 %0, %1, %2, %3;" : "=l"(d) : "l"(a), "l"(b), "l"(c)); return d;
}
__device__ __forceinline__ float ex2(float x) {
    float r; asm("ex2.approx.ftz.f32 %0, %1;" : "=f"(r) : "f"(x)); return r;
}
__device__ __forceinline__ void cp16(float* dst, const float* src) {
    unsigned d = (unsigned)__cvta_generic_to_shared(dst);
    asm volatile("cp.async.cg.shared.global [%0], [%1], 16;" :: "r"(d), "l"(src));
}

// -------- stage 0: zero output + stats (graph replays need reset) --------
__global__ void k_zero(float* __restrict__ out) {
    int i = blockIdx.x * 256 + threadIdx.x;
    if (i < NTEST) out[i] = 0.f;
    if (i < D) { g_colsum[i] = 0.0; g_colsumsq[i] = 0.0; }
}

// -------- stage 1: per-column sum / sumsq over train --------
__global__ void k_colstats(const float* __restrict__ train) {
    int c = threadIdx.x;
    int rbase = blockIdx.x * 64;
    double s = 0.0, s2 = 0.0;
#pragma unroll 4
    for (int r = 0; r < 64; ++r) {
        float v = train[(rbase + r) * D + c];
        s += (double)v;
        s2 += (double)v * (double)v;
    }
    atomicAdd(&g_colsum[c], s);
    atomicAdd(&g_colsumsq[c], s2);
}

// -------- stage 2: bandwidth (Scott) + normalizer Z --------
__global__ void k_finalize() {
    int c = threadIdx.x;
    const double n = (double)NTRAIN;
    double mean = g_colsum[c] / n;
    double var  = (g_colsumsq[c] - n * mean * mean) / (n - 1.0);
    double sd   = sqrt(fmax(var, 0.0));
    sd = fmax(sd, 0.01);
    double bw = 1.06 * sd * exp(-log(n) / (4.0 + (double)D));
    bw = fmin(bw, 0.49);
    g_inv_bw[c] = (float)(1.0 / bw);

    __shared__ double red[D];
    red[c] = log(bw);
    __syncthreads();
    for (int off = 64; off; off >>= 1) {
        if (c < off) red[c] += red[c + off];
        __syncthreads();
    }
    if (c == 0) {
        double Z = 0.5 * (double)D * log(2.0 * 3.14159265358979323846) + red[0] + log(n);
        g_Z = (float)Z;
    }
}

// -------- stage 3: scale by 1/bw, transpose to k-major, row norms --------
__global__ void k_scale(const float* __restrict__ test, const float* __restrict__ train) {
    int r = blockIdx.x;
    int c = threadIdx.x;
    const float* src; float* dstT; float* nrm; int nrows;
    if (r < NTEST) { src = test;  dstT = g_tT;  nrm = g_tnorm;  nrows = NTEST; }
    else { r -= NTEST; src = train; dstT = g_trT; nrm = g_trnorm; nrows = NTRAIN; }

    float v = src[r * D + c] * g_inv_bw[c];
    dstT[c * nrows + r] = v;

    float s = v * v;
#pragma unroll
    for (int off = 16; off; off >>= 1) s += __shfl_down_sync(0xffffffffu, s, off);
    __shared__ float ws[4];
    if ((c & 31) == 0) ws[c >> 5] = s;
    __syncthreads();
    if (c == 0) nrm[r] = ws[0] + ws[1] + ws[2] + ws[3];
}

// -------- stage 4: persistent fused distance-GEMM + exp + reduce --------
extern __shared__ float smem[];

__global__ void __launch_bounds__(256, 1) k_main(float* __restrict__ out) {
    float* As  = smem;                 // [k][m] 128x128
    float* Bs0 = smem + TM * D;        // [k][n] 128x128 (double buffered)
    float* Bs1 = Bs0 + TN * D;
    __shared__ float sred[TM];

    const int tid = threadIdx.x;
    const int tx = tid & 15, ty = tid >> 4;

    const int G = gridDim.x, b = blockIdx.x;
    const int per = NJOBS / G, rem = NJOBS % G;
    const int lo = b * per + min(b, rem);
    const int hi = lo + per + (b < rem ? 1 : 0);
    if (lo >= hi) return;

    const float Zf = g_Z;
    const float c0 = -0.72134752f / Zf;  // -0.5 * log2(e) / Z
    const float c1 = -1.44269504f;       // -log2(e)

    float accR[8];
#pragma unroll
    for (int i = 0; i < 8; ++i) accR[i] = 0.f;

    // prefetch B tile for first job
    {
        int n0 = (lo & (NCHUNKS - 1)) * TN;
#pragma unroll
        for (int s = 0; s < 16; ++s) {
            int i = tid + 256 * s;
            int k = i >> 5, col = (i & 31) << 2;
            cp16(Bs0 + k * TN + col, g_trT + k * NTRAIN + n0 + col);
        }
        asm volatile("cp.async.commit_group;");
    }

    int cur_m = -1;
    int buf = 0;
    float tn8[8];

    for (int job = lo; job < hi; ++job) {
        const int mt = job >> 7;             // / NCHUNKS
        const int nc = job & (NCHUNKS - 1);
        const int mbase = mt * TM, nbase = nc * TN;

        if (mt != cur_m) {
            if (cur_m >= 0) {
                __syncthreads();
                if (tid < TM) sred[tid] = 0.f;
                __syncthreads();
#pragma unroll
                for (int h = 0; h < 2; ++h)
#pragma unroll
                    for (int i = 0; i < 4; ++i)
                        atomicAdd(&sred[h * 64 + 4 * ty + i], accR[h * 4 + i]);
                __syncthreads();
                if (tid < TM) atomicAdd(&out[cur_m * TM + tid], sred[tid]);
#pragma unroll
                for (int i = 0; i < 8; ++i) accR[i] = 0.f;
            }
            __syncthreads();
            // load A tile (plain loads; happens at most twice per block)
#pragma unroll
            for (int s = 0; s < 16; ++s) {
                int i = tid + 256 * s;
                int k = i >> 5, col = (i & 31) << 2;
                *(float4*)(As + k * TM + col) =
                    *(const float4*)(g_tT + k * NTEST + mbase + col);
            }
#pragma unroll
            for (int h = 0; h < 2; ++h)
#pragma unroll
                for (int i = 0; i < 4; ++i)
                    tn8[h * 4 + i] = g_tnorm[mbase + h * 64 + 4 * ty + i];
            cur_m = mt;
        }

        // prefetch next job's B into the other buffer
        if (job + 1 < hi) {
            int n1 = ((job + 1) & (NCHUNKS - 1)) * TN;
            float* Bnext = (buf ? Bs0 : Bs1);
#pragma unroll
            for (int s = 0; s < 16; ++s) {
                int i = tid + 256 * s;
                int k = i >> 5, col = (i & 31) << 2;
                cp16(Bnext + k * TN + col, g_trT + k * NTRAIN + n1 + col);
            }
            asm volatile("cp.async.commit_group;");
            asm volatile("cp.async.wait_group 1;");
        } else {
            asm volatile("cp.async.wait_group 0;");
        }
        __syncthreads();

        const float* Bp = (buf ? Bs1 : Bs0);

        u64 acc[2][2][8];
        const u64 z = pk2(0.f, 0.f);
#pragma unroll
        for (int h = 0; h < 2; ++h)
#pragma unroll
            for (int p = 0; p < 2; ++p)
#pragma unroll
                for (int j = 0; j < 8; ++j) acc[h][p][j] = z;

#pragma unroll 4
        for (int k = 0; k < D; ++k) {
            float4 a0 = *(const float4*)(As + k * TM + 4 * ty);
            float4 a1 = *(const float4*)(As + k * TM + 64 + 4 * ty);
            float4 b0 = *(const float4*)(Bp + k * TN + 4 * tx);
            float4 b1 = *(const float4*)(Bp + k * TN + 64 + 4 * tx);
            u64 A2[2][2] = { { pk2(a0.x, a0.y), pk2(a0.z, a0.w) },
                             { pk2(a1.x, a1.y), pk2(a1.z, a1.w) } };
            u64 B2[8] = { pk2(b0.x, b0.x), pk2(b0.y, b0.y), pk2(b0.z, b0.z), pk2(b0.w, b0.w),
                          pk2(b1.x, b1.x), pk2(b1.y, b1.y), pk2(b1.z, b1.z), pk2(b1.w, b1.w) };
#pragma unroll
            for (int h = 0; h < 2; ++h)
#pragma unroll
                for (int p = 0; p < 2; ++p)
#pragma unroll
                    for (int j = 0; j < 8; ++j)
                        acc[h][p][j] = ffma2(A2[h][p], B2[j], acc[h][p][j]);
        }

        // fused epilogue: sq -> exp -> register accumulate
        float trn8[8];
#pragma unroll
        for (int g = 0; g < 2; ++g)
#pragma unroll
            for (int j = 0; j < 4; ++j)
                trn8[g * 4 + j] = g_trnorm[nbase + g * 64 + 4 * tx + j];

#pragma unroll
        for (int h = 0; h < 2; ++h)
#pragma unroll
            for (int p = 0; p < 2; ++p) {
                float tA = tn8[h * 4 + 2 * p];
                float tB = tn8[h * 4 + 2 * p + 1];
                float sA = 0.f, sB = 0.f;
#pragma unroll
                for (int j = 0; j < 8; ++j) {
                    float d0, d1; upk2(acc[h][p][j], d0, d1);
                    float s0 = fmaf(-2.f, d0, tA + trn8[j]);
                    float s1 = fmaf(-2.f, d1, tB + trn8[j]);
                    s0 = fmaxf(s0, 0.f);
                    s1 = fmaxf(s1, 0.f);
                    sA += ex2(fmaf(s0, c0, c1));
                    sB += ex2(fmaf(s1, c0, c1));
                }
                accR[h * 4 + 2 * p]     += sA;
                accR[h * 4 + 2 * p + 1] += sB;
            }

        buf ^= 1;
        __syncthreads();  // protect Bp reads before next iteration's cp.async
    }

    // final flush
    __syncthreads();
    if (tid < TM) sred[tid] = 0.f;
    __syncthreads();
#pragma unroll
    for (int h = 0; h < 2; ++h)
#pragma unroll
        for (int i = 0; i < 4; ++i)
            atomicAdd(&sred[h * 64 + 4 * ty + i], accR[h * 4 + i]);
    __syncthreads();
    if (tid < TM) atomicAdd(&out[cur_m * TM + tid], sred[tid]);
}

extern "C" void kernel_launch(void* const* d_in, const int* in_sizes, int n_in,
                              void* d_out, int out_size) {
    const float* test  = (const float*)d_in[0];
    const float* train = (const float*)d_in[1];
    float* out = (float*)d_out;
    (void)in_sizes; (void)n_in; (void)out_size;

    int dev = 0;
    cudaGetDevice(&dev);
    int smc = 148;
    cudaDeviceGetAttribute(&smc, cudaDevAttrMultiProcessorCount, dev);

    const size_t shmem = (size_t)(TM * D + 2 * TN * D) * sizeof(float);  // 192 KB
    cudaFuncSetAttribute(k_main, cudaFuncAttributeMaxDynamicSharedMemorySize, (int)shmem);

    k_zero<<<(NTEST + 255) / 256, 256>>>(out);
    k_colstats<<<NTRAIN / 64, 128>>>(train);
    k_finalize<<<1, 128>>>();
    k_scale<<<NTEST + NTRAIN, 128>>>(test, train);
    k_main<<<smc, 256, shmem>>>(out);
}

// round 5
// speedup vs baseline: 1.8185x; 1.8185x over previous
#include <cuda_runtime.h>
#include <cuda_fp16.h>
#include <cstdint>

#define D        128
#define NTEST    4096
#define NTRAIN   16384
#define TM       128
#define TN       128
#define MTILES   (NTEST / TM)      // 32
#define NTILES   (NTRAIN / TN)     // 128
#define NJOBS    (MTILES * NTILES) // 4096
#define NTHREADS 256

// ---------------- device scratch ----------------
__device__ double g_colsum[D];
__device__ double g_colsumsq[D];
__device__ float  g_inv_bw[D];
__device__ float  g_Z;
__device__ __half g_Ah1[NTEST * D];
__device__ __half g_Ah2[NTEST * D];
__device__ __half g_Bh1[NTRAIN * D];
__device__ __half g_Bh2[NTRAIN * D];
__device__ float  g_tnorm[NTEST];
__device__ float  g_trnorm[NTRAIN];

// ---------------- helpers ----------------
__device__ __forceinline__ uint32_t smem_u32(const void* p) {
    uint32_t a;
    asm("{ .reg .u64 t; cvta.to.shared.u64 t, %1; cvt.u32.u64 %0, t; }" : "=r"(a) : "l"(p));
    return a;
}
__device__ __forceinline__ void cp16s(uint32_t dst, const void* src) {
    asm volatile("cp.async.cg.shared.global [%0], [%1], 16;" :: "r"(dst), "l"(src));
}
__device__ __forceinline__ float ex2(float x) {
    float r; asm("ex2.approx.ftz.f32 %0, %1;" : "=f"(r) : "f"(x)); return r;
}
__device__ __forceinline__ void ldsm_x4(uint32_t (&r)[4], uint32_t addr) {
    asm volatile("ldmatrix.sync.aligned.m8n8.x4.shared.b16 {%0,%1,%2,%3}, [%4];"
                 : "=r"(r[0]), "=r"(r[1]), "=r"(r[2]), "=r"(r[3]) : "r"(addr));
}
__device__ __forceinline__ void mma16816(float (&d)[4], const uint32_t (&a)[4],
                                         uint32_t b0, uint32_t b1) {
    asm volatile("mma.sync.aligned.m16n8k16.row.col.f32.f16.f16.f32 "
                 "{%0,%1,%2,%3}, {%4,%5,%6,%7}, {%8,%9}, {%0,%1,%2,%3};"
                 : "+f"(d[0]), "+f"(d[1]), "+f"(d[2]), "+f"(d[3])
                 : "r"(a[0]), "r"(a[1]), "r"(a[2]), "r"(a[3]), "r"(b0), "r"(b1));
}

// ---------------- SMEM layout ----------------
// A: [0, 65536)      limb0 32KB | limb1 32KB      (row-major [m][k], 16B-group XOR swizzle)
// B: [65536, 196608) buf0 (h1 32KB | h2 32KB), buf1 (same)
// trn: [196608, 197632) 2 x 512B
#define SM_A     0
#define SM_B     65536
#define SM_TRN   196608
#define SM_TOTAL 197632

// -------- stage 0: zero output + stats --------
__global__ void k_zero(float* __restrict__ out) {
    int i = blockIdx.x * 256 + threadIdx.x;
    if (i < NTEST) out[i] = 0.f;
    if (i < D) { g_colsum[i] = 0.0; g_colsumsq[i] = 0.0; }
}

// -------- stage 1: per-column sum / sumsq over train --------
__global__ void k_colstats(const float* __restrict__ train) {
    int c = threadIdx.x;
    int rbase = blockIdx.x * 64;
    double s = 0.0, s2 = 0.0;
#pragma unroll 4
    for (int r = 0; r < 64; ++r) {
        float v = train[(rbase + r) * D + c];
        s += (double)v;
        s2 += (double)v * (double)v;
    }
    atomicAdd(&g_colsum[c], s);
    atomicAdd(&g_colsumsq[c], s2);
}

// -------- stage 2: bandwidth + Z --------
__global__ void k_finalize() {
    int c = threadIdx.x;
    const double n = (double)NTRAIN;
    double mean = g_colsum[c] / n;
    double var  = (g_colsumsq[c] - n * mean * mean) / (n - 1.0);
    double sd   = sqrt(fmax(var, 0.0));
    sd = fmax(sd, 0.01);
    double bw = 1.06 * sd * exp(-log(n) / (4.0 + (double)D));
    bw = fmin(bw, 0.49);
    g_inv_bw[c] = (float)(1.0 / bw);

    __shared__ double red[D];
    red[c] = log(bw);
    __syncthreads();
    for (int off = 64; off; off >>= 1) {
        if (c < off) red[c] += red[c + off];
        __syncthreads();
    }
    if (c == 0) {
        double Z = 0.5 * (double)D * log(2.0 * 3.14159265358979323846) + red[0] + log(n);
        g_Z = (float)Z;
    }
}

// -------- stage 3: scale, fp16 two-limb split (coalesced), norms --------
__global__ void k_split(const float* __restrict__ test, const float* __restrict__ train) {
    int r = blockIdx.x;
    int c = threadIdx.x;
    const float* src; __half *d1, *d2; float* nrm;
    if (r < NTEST) { src = test;  d1 = g_Ah1; d2 = g_Ah2; nrm = g_tnorm; }
    else { r -= NTEST; src = train; d1 = g_Bh1; d2 = g_Bh2; nrm = g_trnorm; }

    float v = src[r * D + c] * g_inv_bw[c];
    __half h1 = __float2half_rn(v);
    float res = v - __half2float(h1);
    __half h2 = __float2half_rn(res);
    d1[r * D + c] = h1;
    d2[r * D + c] = h2;

    float s = v * v;
#pragma unroll
    for (int off = 16; off; off >>= 1) s += __shfl_down_sync(0xffffffffu, s, off);
    __shared__ float ws[4];
    if ((c & 31) == 0) ws[c >> 5] = s;
    __syncthreads();
    if (c == 0) nrm[r] = ws[0] + ws[1] + ws[2] + ws[3];
}

// -------- stage 4: persistent HMMA (mma.sync) split-fp16 GEMM + fused KDE epilogue --------
extern __shared__ char smem[];

__global__ void __launch_bounds__(NTHREADS, 1) k_main(float* __restrict__ out) {
    const uint32_t sb = smem_u32(smem);
    const int tid = threadIdx.x, lane = tid & 31, wid = tid >> 5;
    const int wm = wid & 3, wn = wid >> 2;   // warp tile: rows wm*32, cols wn*64
    const int qr = lane >> 2, qc = lane & 3;

    // job range (contiguous, m-major)
    const int G = gridDim.x, b = blockIdx.x;
    const int per = NJOBS / G, rem = NJOBS % G;
    const int lo = b * per + min(b, rem);
    const int nloc = per + (b < rem ? 1 : 0);
    if (nloc <= 0) return;

    const float Zf = g_Z;
    const float c0v = -0.72134752f / Zf;  // -0.5*log2(e)/Z
    const float c1v = -1.44269504f;       // -log2(e)

    // rows this thread owns in the epilogue: i = im*2+h -> wm*32 + im*16 + h*8 + qr
    int rowid[4];
#pragma unroll
    for (int i = 0; i < 4; ++i) rowid[i] = wm * 32 + (i >> 1) * 16 + (i & 1) * 8 + qr;

    // ldmatrix address components (constant per thread)
    const int arow = wm * 32 + (lane & 15);          // A frag row (im adds +16)
    const int akg  = lane >> 4;                      // A k-group half
    const int nofs = (lane & 7) + ((lane >> 4) << 3);// B frag n offset within 16
    const int bkg  = (lane >> 3) & 1;                // B k-group half

    auto loadA = [&](int mbase) {
        for (int i = tid; i < 4096; i += NTHREADS) {
            int l = i >> 11, idx = i & 2047;
            int r = idx >> 4, g = idx & 15;
            const __half* src = (l ? g_Ah2 : g_Ah1) + (size_t)(mbase + r) * D + g * 8;
            cp16s(sb + SM_A + l * 32768 + (uint32_t)(r * 256 + ((g ^ (r & 7)) << 4)), src);
        }
        asm volatile("cp.async.commit_group;" ::: "memory");
        asm volatile("cp.async.wait_all;" ::: "memory");
        __syncthreads();
    };
    auto loadB = [&](int nt, int buf) {
        int nbase = nt * TN;
        uint32_t bb = sb + SM_B + buf * 65536;
        for (int i = tid; i < 4096; i += NTHREADS) {
            int l = i >> 11, idx = i & 2047;
            int r = idx >> 4, g = idx & 15;
            const __half* src = (l ? g_Bh2 : g_Bh1) + (size_t)(nbase + r) * D + g * 8;
            cp16s(bb + l * 32768 + (uint32_t)(r * 256 + ((g ^ (r & 7)) << 4)), src);
        }
        if (tid < 32)
            cp16s(sb + SM_TRN + buf * 512 + tid * 16, g_trnorm + nbase + tid * 4);
        asm volatile("cp.async.commit_group;" ::: "memory");
    };

    float acc[2][8][4];
    float accR[4] = {0.f, 0.f, 0.f, 0.f};
    float tnr[4];

    int cur_m = lo >> 7;  // / NTILES
    loadA(cur_m * TM);
    loadB(lo & (NTILES - 1), 0);
#pragma unroll
    for (int i = 0; i < 4; ++i) tnr[i] = g_tnorm[cur_m * TM + rowid[i]];

    for (int t = 0; t < nloc; ++t) {
        const int job = lo + t;
        const int mt = job >> 7;
        const int buf = t & 1;

        if (mt != cur_m) {
            // flush finished m tile
            if (qc == 0) {
#pragma unroll
                for (int i = 0; i < 4; ++i) {
                    atomicAdd(&out[cur_m * TM + rowid[i]], accR[i]);
                    accR[i] = 0.f;
                }
            } else {
#pragma unroll
                for (int i = 0; i < 4; ++i) accR[i] = 0.f;
            }
            __syncthreads();   // all warps done reading old A
            loadA(mt * TM);    // includes wait_all + sync (also drains B prefetch; rare)
            cur_m = mt;
#pragma unroll
            for (int i = 0; i < 4; ++i) tnr[i] = g_tnorm[cur_m * TM + rowid[i]];
        }

        asm volatile("cp.async.wait_group 0;" ::: "memory");
        __syncthreads();   // current B buffer ready; prev compute done everywhere

        if (t + 1 < nloc) loadB((job + 1) & (NTILES - 1), buf ^ 1);

        // ---- 3 GEMM passes: A1*B1 + A1*B2 + A2*B1 ----
#pragma unroll
        for (int im = 0; im < 2; ++im)
#pragma unroll
            for (int jn = 0; jn < 8; ++jn)
#pragma unroll
                for (int e = 0; e < 4; ++e) acc[im][jn][e] = 0.f;

        const uint32_t A0 = sb + SM_A, A1 = A0 + 32768;
        const uint32_t Bb = sb + SM_B + buf * 65536;
        const uint32_t passA[3] = {A0, A0, A1};
        const uint32_t passB[3] = {Bb, Bb + 32768, Bb};

#pragma unroll
        for (int ps = 0; ps < 3; ++ps) {
            const uint32_t Ab = passA[ps], Bp = passB[ps];
#pragma unroll
            for (int ks = 0; ks < 8; ++ks) {
                uint32_t a[2][4];
#pragma unroll
                for (int im = 0; im < 2; ++im) {
                    int row = arow + im * 16;
                    int g = ks * 2 + akg;
                    ldsm_x4(a[im], Ab + (uint32_t)(row * 256 + ((g ^ (row & 7)) << 4)));
                }
                uint32_t bfr[4][4];
#pragma unroll
                for (int j = 0; j < 4; ++j) {
                    int row = wn * 64 + j * 16 + nofs;
                    int g = ks * 2 + bkg;
                    ldsm_x4(bfr[j], Bp + (uint32_t)(row * 256 + ((g ^ (row & 7)) << 4)));
                }
#pragma unroll
                for (int im = 0; im < 2; ++im)
#pragma unroll
                    for (int jn = 0; jn < 8; ++jn)
                        mma16816(acc[im][jn], a[im],
                                 bfr[jn >> 1][(jn & 1) * 2], bfr[jn >> 1][(jn & 1) * 2 + 1]);
            }
        }

        // ---- fused epilogue ----
        const float* trn = (const float*)(smem + SM_TRN + buf * 512);
#pragma unroll
        for (int im = 0; im < 2; ++im)
#pragma unroll
            for (int h = 0; h < 2; ++h) {
                float s = 0.f;
                const float tv = tnr[im * 2 + h];
#pragma unroll
                for (int jn = 0; jn < 8; ++jn) {
                    int n0 = wn * 64 + jn * 8 + qc * 2;
                    float d0 = acc[im][jn][2 * h], d1 = acc[im][jn][2 * h + 1];
                    float s0 = fmaxf(fmaf(-2.f, d0, tv + trn[n0]), 0.f);
                    float s1 = fmaxf(fmaf(-2.f, d1, tv + trn[n0 + 1]), 0.f);
                    s += ex2(fmaf(s0, c0v, c1v));
                    s += ex2(fmaf(s1, c0v, c1v));
                }
                s += __shfl_xor_sync(0xffffffffu, s, 1);
                s += __shfl_xor_sync(0xffffffffu, s, 2);
                if (qc == 0) accR[im * 2 + h] += s;
            }
    }

    // final flush
    if (qc == 0) {
#pragma unroll
        for (int i = 0; i < 4; ++i)
            atomicAdd(&out[cur_m * TM + rowid[i]], accR[i]);
    }
}

extern "C" void kernel_launch(void* const* d_in, const int* in_sizes, int n_in,
                              void* d_out, int out_size) {
    const float* test  = (const float*)d_in[0];
    const float* train = (const float*)d_in[1];
    float* out = (float*)d_out;
    (void)in_sizes; (void)n_in; (void)out_size;

    int dev = 0;
    cudaGetDevice(&dev);
    int smc = 148;
    cudaDeviceGetAttribute(&smc, cudaDevAttrMultiProcessorCount, dev);

    cudaFuncSetAttribute(k_main, cudaFuncAttributeMaxDynamicSharedMemorySize, SM_TOTAL);

    k_zero<<<(NTEST + 255) / 256, 256>>>(out);
    k_colstats<<<NTRAIN / 64, 128>>>(train);
    k_finalize<<<1, 128>>>();
    k_split<<<NTEST + NTRAIN, 128>>>(test, train);
    k_main<<<smc, NTHREADS, SM_TOTAL>>>(out);
}

// round 6
// speedup vs baseline: 1.9496x; 1.0721x over previous
#include <cuda_runtime.h>
#include <cuda_fp16.h>
#include <cstdint>

#define D        128
#define NTEST    4096
#define NTRAIN   16384
#define TM       128
#define TN       128
#define MTILES   (NTEST / TM)      // 32
#define NTILES   (NTRAIN / TN)     // 128
#define NJOBS    (MTILES * NTILES) // 4096
#define NTHREADS 256

// ---------------- device scratch (zero-initialized at module load) ----------------
__device__ double g_colsum[D];
__device__ double g_colsumsq[D];
__device__ float  g_inv_bw[D];
__device__ float  g_Z;
__device__ __half g_Ah1[NTEST * D];
__device__ __half g_Ah2[NTEST * D];
__device__ __half g_Bh1[NTRAIN * D];
__device__ __half g_Bh2[NTRAIN * D];
__device__ float  g_tnorm[NTEST];
__device__ float  g_trnorm[NTRAIN];

// ---------------- helpers ----------------
__device__ __forceinline__ uint32_t smem_u32(const void* p) {
    uint32_t a;
    asm("{ .reg .u64 t; cvta.to.shared.u64 t, %1; cvt.u32.u64 %0, t; }" : "=r"(a) : "l"(p));
    return a;
}
__device__ __forceinline__ void cp16s(uint32_t dst, const void* src) {
    asm volatile("cp.async.cg.shared.global [%0], [%1], 16;" :: "r"(dst), "l"(src));
}
__device__ __forceinline__ float ex2(float x) {
    float r; asm("ex2.approx.ftz.f32 %0, %1;" : "=f"(r) : "f"(x)); return r;
}
__device__ __forceinline__ void ldsm_x4(uint32_t (&r)[4], uint32_t addr) {
    asm volatile("ldmatrix.sync.aligned.m8n8.x4.shared.b16 {%0,%1,%2,%3}, [%4];"
                 : "=r"(r[0]), "=r"(r[1]), "=r"(r[2]), "=r"(r[3]) : "r"(addr));
}
__device__ __forceinline__ void mma16816(float (&d)[4], const uint32_t (&a)[4],
                                         uint32_t b0, uint32_t b1) {
    asm volatile("mma.sync.aligned.m16n8k16.row.col.f32.f16.f16.f32 "
                 "{%0,%1,%2,%3}, {%4,%5,%6,%7}, {%8,%9}, {%0,%1,%2,%3};"
                 : "+f"(d[0]), "+f"(d[1]), "+f"(d[2]), "+f"(d[3])
                 : "r"(a[0]), "r"(a[1]), "r"(a[2]), "r"(a[3]), "r"(b0), "r"(b1));
}

// ---------------- SMEM layout (k_main) ----------------
#define SM_A     0
#define SM_B     65536
#define SM_TRN   196608
#define SM_TOTAL 197632

// -------- launch 1: per-column sum / sumsq over train (coalesced float4) --------
// grid 64, block 128 (4 warps). warp w covers rows {b*256 + w + 4i}; lane covers cols 4l..4l+3.
__global__ void k_colstats(const float* __restrict__ train) {
    const int warp = threadIdx.x >> 5, lane = threadIdx.x & 31;
    const int c4 = lane * 4;
    double s[4] = {0, 0, 0, 0}, s2[4] = {0, 0, 0, 0};
    const int rbase = blockIdx.x * 256 + warp;
#pragma unroll 4
    for (int i = 0; i < 64; ++i) {
        float4 v = *(const float4*)(train + (size_t)(rbase + i * 4) * D + c4);
        s[0] += v.x; s2[0] += (double)v.x * v.x;
        s[1] += v.y; s2[1] += (double)v.y * v.y;
        s[2] += v.z; s2[2] += (double)v.z * v.z;
        s[3] += v.w; s2[3] += (double)v.w * v.w;
    }
    __shared__ double sh[2][4][D];
#pragma unroll
    for (int j = 0; j < 4; ++j) { sh[0][warp][c4 + j] = s[j]; sh[1][warp][c4 + j] = s2[j]; }
    __syncthreads();
    const int c = threadIdx.x;  // 128 threads = 128 cols
    double a = 0, b2 = 0;
#pragma unroll
    for (int w = 0; w < 4; ++w) { a += sh[0][w][c]; b2 += sh[1][w][c]; }
    atomicAdd(&g_colsum[c], a);
    atomicAdd(&g_colsumsq[c], b2);
}

// -------- launch 2: bandwidth + Z; then re-arm state for next replay --------
__global__ void k_finalize(float* __restrict__ out) {
    int c = threadIdx.x;
    const double n = (double)NTRAIN;
    double mean = g_colsum[c] / n;
    double var  = (g_colsumsq[c] - n * mean * mean) / (n - 1.0);
    double sd   = sqrt(fmax(var, 0.0));
    sd = fmax(sd, 0.01);
    double bw = 1.06 * sd * exp(-log(n) / (4.0 + (double)D));
    bw = fmin(bw, 0.49);
    g_inv_bw[c] = (float)(1.0 / bw);

    __shared__ double red[D];
    red[c] = log(bw);
    __syncthreads();
    for (int off = 64; off; off >>= 1) {
        if (c < off) red[c] += red[c + off];
        __syncthreads();
    }
    if (c == 0) {
        double Z = 0.5 * (double)D * log(2.0 * 3.14159265358979323846) + red[0] + log(n);
        g_Z = (float)Z;
    }
    // re-arm for next graph replay (stats consumed above)
    g_colsum[c] = 0.0;
    g_colsumsq[c] = 0.0;
    for (int i = c; i < NTEST; i += 128) out[i] = 0.f;
}

// -------- launch 3: scale, fp16 two-limb split, norms (warp-per-row, float4) --------
__global__ void k_split(const float* __restrict__ test, const float* __restrict__ train) {
    const int lane = threadIdx.x & 31;
    const int r = blockIdx.x * 8 + (threadIdx.x >> 5);
    const float* src; __half *d1, *d2; float* nrm; int rr = r;
    if (r < NTEST) { src = test;  d1 = g_Ah1; d2 = g_Ah2; nrm = g_tnorm; }
    else { rr = r - NTEST; src = train; d1 = g_Bh1; d2 = g_Bh2; nrm = g_trnorm; }

    const int c4 = lane * 4;
    float4 v = *(const float4*)(src + (size_t)rr * D + c4);
    float4 w = *(const float4*)(g_inv_bw + c4);
    v.x *= w.x; v.y *= w.y; v.z *= w.z; v.w *= w.w;

    __half2 p1a = __floats2half2_rn(v.x, v.y);
    __half2 p1b = __floats2half2_rn(v.z, v.w);
    float2 f1a = __half22float2(p1a), f1b = __half22float2(p1b);
    __half2 p2a = __floats2half2_rn(v.x - f1a.x, v.y - f1a.y);
    __half2 p2b = __floats2half2_rn(v.z - f1b.x, v.w - f1b.y);

    *(__half2*)(d1 + (size_t)rr * D + c4)     = p1a;
    *(__half2*)(d1 + (size_t)rr * D + c4 + 2) = p1b;
    *(__half2*)(d2 + (size_t)rr * D + c4)     = p2a;
    *(__half2*)(d2 + (size_t)rr * D + c4 + 2) = p2b;

    float s = v.x * v.x + v.y * v.y + v.z * v.z + v.w * v.w;
#pragma unroll
    for (int off = 16; off; off >>= 1) s += __shfl_xor_sync(0xffffffffu, s, off);
    if (lane == 0) nrm[rr] = s;
}

// -------- launch 4: persistent HMMA split-fp16 GEMM + fused KDE epilogue --------
extern __shared__ char smem[];

__global__ void __launch_bounds__(NTHREADS, 1) k_main(float* __restrict__ out) {
    const uint32_t sb = smem_u32(smem);
    const int tid = threadIdx.x, lane = tid & 31, wid = tid >> 5;
    const int wm = wid & 3, wn = wid >> 2;   // warp tile: rows wm*32, cols wn*64
    const int qr = lane >> 2, qc = lane & 3;

    const int G = gridDim.x, b = blockIdx.x;
    const int per = NJOBS / G, rem = NJOBS % G;
    const int lo = b * per + min(b, rem);
    const int nloc = per + (b < rem ? 1 : 0);
    if (nloc <= 0) return;

    const float Zf = g_Z;
    const float c0v = -0.72134752f / Zf;  // -0.5*log2(e)/Z
    const float c1v = -1.44269504f;       // -log2(e)

    int rowid[4];
#pragma unroll
    for (int i = 0; i < 4; ++i) rowid[i] = wm * 32 + (i >> 1) * 16 + (i & 1) * 8 + qr;

    const int arow = wm * 32 + (lane & 15);
    const int akg  = lane >> 4;
    const int nofs = (lane & 7) + ((lane >> 4) << 3);
    const int bkg  = (lane >> 3) & 1;

    auto loadA = [&](int mbase) {
        for (int i = tid; i < 4096; i += NTHREADS) {
            int l = i >> 11, idx = i & 2047;
            int r = idx >> 4, g = idx & 15;
            const __half* src = (l ? g_Ah2 : g_Ah1) + (size_t)(mbase + r) * D + g * 8;
            cp16s(sb + SM_A + l * 32768 + (uint32_t)(r * 256 + ((g ^ (r & 7)) << 4)), src);
        }
        asm volatile("cp.async.commit_group;" ::: "memory");
        asm volatile("cp.async.wait_all;" ::: "memory");
        __syncthreads();
    };
    auto loadB = [&](int nt, int buf) {
        int nbase = nt * TN;
        uint32_t bb = sb + SM_B + buf * 65536;
        for (int i = tid; i < 4096; i += NTHREADS) {
            int l = i >> 11, idx = i & 2047;
            int r = idx >> 4, g = idx & 15;
            const __half* src = (l ? g_Bh2 : g_Bh1) + (size_t)(nbase + r) * D + g * 8;
            cp16s(bb + l * 32768 + (uint32_t)(r * 256 + ((g ^ (r & 7)) << 4)), src);
        }
        if (tid < 32)
            cp16s(sb + SM_TRN + buf * 512 + tid * 16, g_trnorm + nbase + tid * 4);
        asm volatile("cp.async.commit_group;" ::: "memory");
    };

    float acc[2][8][4];
    float accR[4] = {0.f, 0.f, 0.f, 0.f};
    float tnr[4];

    int cur_m = lo >> 7;
    loadA(cur_m * TM);
    loadB(lo & (NTILES - 1), 0);
#pragma unroll
    for (int i = 0; i < 4; ++i) tnr[i] = g_tnorm[cur_m * TM + rowid[i]];

    for (int t = 0; t < nloc; ++t) {
        const int job = lo + t;
        const int mt = job >> 7;
        const int buf = t & 1;

        if (mt != cur_m) {
            if (qc == 0) {
#pragma unroll
                for (int i = 0; i < 4; ++i) {
                    atomicAdd(&out[cur_m * TM + rowid[i]], accR[i]);
                    accR[i] = 0.f;
                }
            } else {
#pragma unroll
                for (int i = 0; i < 4; ++i) accR[i] = 0.f;
            }
            __syncthreads();
            loadA(mt * TM);
            cur_m = mt;
#pragma unroll
            for (int i = 0; i < 4; ++i) tnr[i] = g_tnorm[cur_m * TM + rowid[i]];
        }

        asm volatile("cp.async.wait_group 0;" ::: "memory");
        __syncthreads();

        if (t + 1 < nloc) loadB((job + 1) & (NTILES - 1), buf ^ 1);

#pragma unroll
        for (int im = 0; im < 2; ++im)
#pragma unroll
            for (int jn = 0; jn < 8; ++jn)
#pragma unroll
                for (int e = 0; e < 4; ++e) acc[im][jn][e] = 0.f;

        const uint32_t A0 = sb + SM_A, A1 = A0 + 32768;
        const uint32_t B0 = sb + SM_B + buf * 65536, B1 = B0 + 32768;

        // fused 3-limb mainloop: acc += A0*B0 + A0*B1 + A1*B0, fragments loaded once
#pragma unroll
        for (int ks = 0; ks < 8; ++ks) {
            const int ga = ks * 2 + akg, gb = ks * 2 + bkg;
            uint32_t a0[2][4], a1[2][4];
#pragma unroll
            for (int im = 0; im < 2; ++im) {
                int row = arow + im * 16;
                uint32_t off = (uint32_t)(row * 256 + ((ga ^ (row & 7)) << 4));
                ldsm_x4(a0[im], A0 + off);
                ldsm_x4(a1[im], A1 + off);
            }
            uint32_t b0f[4][4], b1f[4][4];
#pragma unroll
            for (int j = 0; j < 4; ++j) {
                int row = wn * 64 + j * 16 + nofs;
                uint32_t off = (uint32_t)(row * 256 + ((gb ^ (row & 7)) << 4));
                ldsm_x4(b0f[j], B0 + off);
                ldsm_x4(b1f[j], B1 + off);
            }
#pragma unroll
            for (int im = 0; im < 2; ++im)
#pragma unroll
                for (int jn = 0; jn < 8; ++jn) {
                    uint32_t lo0 = b0f[jn >> 1][(jn & 1) * 2], hi0 = b0f[jn >> 1][(jn & 1) * 2 + 1];
                    uint32_t lo1 = b1f[jn >> 1][(jn & 1) * 2], hi1 = b1f[jn >> 1][(jn & 1) * 2 + 1];
                    mma16816(acc[im][jn], a0[im], lo0, hi0);
                    mma16816(acc[im][jn], a0[im], lo1, hi1);
                    mma16816(acc[im][jn], a1[im], lo0, hi0);
                }
        }

        // fused epilogue
        const float* trn = (const float*)(smem + SM_TRN + buf * 512);
#pragma unroll
        for (int im = 0; im < 2; ++im)
#pragma unroll
            for (int h = 0; h < 2; ++h) {
                float s = 0.f;
                const float tv = tnr[im * 2 + h];
#pragma unroll
                for (int jn = 0; jn < 8; ++jn) {
                    int n0 = wn * 64 + jn * 8 + qc * 2;
                    float d0 = acc[im][jn][2 * h], d1 = acc[im][jn][2 * h + 1];
                    float s0 = fmaxf(fmaf(-2.f, d0, tv + trn[n0]), 0.f);
                    float s1 = fmaxf(fmaf(-2.f, d1, tv + trn[n0 + 1]), 0.f);
                    s += ex2(fmaf(s0, c0v, c1v));
                    s += ex2(fmaf(s1, c0v, c1v));
                }
                s += __shfl_xor_sync(0xffffffffu, s, 1);
                s += __shfl_xor_sync(0xffffffffu, s, 2);
                if (qc == 0) accR[im * 2 + h] += s;
            }
    }

    if (qc == 0) {
#pragma unroll
        for (int i = 0; i < 4; ++i)
            atomicAdd(&out[cur_m * TM + rowid[i]], accR[i]);
    }
}

extern "C" void kernel_launch(void* const* d_in, const int* in_sizes, int n_in,
                              void* d_out, int out_size) {
    const float* test  = (const float*)d_in[0];
    const float* train = (const float*)d_in[1];
    float* out = (float*)d_out;
    (void)in_sizes; (void)n_in; (void)out_size;

    int dev = 0;
    cudaGetDevice(&dev);
    int smc = 148;
    cudaDeviceGetAttribute(&smc, cudaDevAttrMultiProcessorCount, dev);

    cudaFuncSetAttribute(k_main, cudaFuncAttributeMaxDynamicSharedMemorySize, SM_TOTAL);

    // 4 launches; device-global state re-armed by k_finalize each replay
    // (module load zero-inits g_colsum/g_colsumsq for the very first call)
    k_colstats<<<64, 128>>>(train);
    k_finalize<<<1, 128>>>(out);
    k_split<<<(NTEST + NTRAIN) / 8, 256>>>(test, train);
    k_main<<<smc, NTHREADS, SM_TOTAL>>>(out);
}

// round 7
// speedup vs baseline: 2.0461x; 1.0495x over previous
#include <cuda_runtime.h>
#include <cuda_fp16.h>
#include <cstdint>

#define D        128
#define NTEST    4096
#define NTRAIN   16384
#define TM       128
#define TN       64
#define MTILES   (NTEST / TM)      // 32
#define NTILES   (NTRAIN / TN)     // 256
#define NJOBS    (MTILES * NTILES) // 8192
#define NTHREADS 256

// ---------------- device scratch (zero-initialized at module load) ----------------
__device__ double g_colsum[D];
__device__ double g_colsumsq[D];
__device__ float  g_inv_bw[D];
__device__ float  g_Z;
__device__ __half g_Ah1[NTEST * D];
__device__ __half g_Ah2[NTEST * D];
__device__ __half g_Bh1[NTRAIN * D];
__device__ __half g_Bh2[NTRAIN * D];
__device__ float  g_tnorm[NTEST];
__device__ float  g_trnorm[NTRAIN];

// ---------------- helpers ----------------
__device__ __forceinline__ uint32_t smem_u32(const void* p) {
    uint32_t a;
    asm("{ .reg .u64 t; cvta.to.shared.u64 t, %1; cvt.u32.u64 %0, t; }" : "=r"(a) : "l"(p));
    return a;
}
__device__ __forceinline__ void cp16s(uint32_t dst, const void* src) {
    asm volatile("cp.async.cg.shared.global [%0], [%1], 16;" :: "r"(dst), "l"(src));
}
__device__ __forceinline__ float ex2(float x) {
    float r; asm("ex2.approx.ftz.f32 %0, %1;" : "=f"(r) : "f"(x)); return r;
}
__device__ __forceinline__ void ldsm_x4(uint32_t (&r)[4], uint32_t addr) {
    asm volatile("ldmatrix.sync.aligned.m8n8.x4.shared.b16 {%0,%1,%2,%3}, [%4];"
                 : "=r"(r[0]), "=r"(r[1]), "=r"(r[2]), "=r"(r[3]) : "r"(addr));
}
__device__ __forceinline__ void mma16816(float (&d)[4], const uint32_t (&a)[4],
                                         uint32_t b0, uint32_t b1) {
    asm volatile("mma.sync.aligned.m16n8k16.row.col.f32.f16.f16.f32 "
                 "{%0,%1,%2,%3}, {%4,%5,%6,%7}, {%8,%9}, {%0,%1,%2,%3};"
                 : "+f"(d[0]), "+f"(d[1]), "+f"(d[2]), "+f"(d[3])
                 : "r"(a[0]), "r"(a[1]), "r"(a[2]), "r"(a[3]), "r"(b0), "r"(b1));
}

// ---------------- SMEM layout (k_main, per block) ----------------
// A: [0, 65536)          limb0 32KB | limb1 32KB  ([m][k], 16B-group XOR swizzle)
// B: [65536, 98304)      limb0 16KB | limb1 16KB  (single-buffered, 64 rows)
// trn: [98304, 98816)    2 x 256B (double-buffered)
#define SM_A     0
#define SM_B     65536
#define SM_TRN   98304
#define SM_TOTAL 98816

// -------- launch 1: per-column sum / sumsq over train (coalesced float4) --------
__global__ void k_colstats(const float* __restrict__ train) {
    const int warp = threadIdx.x >> 5, lane = threadIdx.x & 31;
    const int c4 = lane * 4;
    double s[4] = {0, 0, 0, 0}, s2[4] = {0, 0, 0, 0};
    const int rbase = blockIdx.x * 256 + warp;
#pragma unroll 4
    for (int i = 0; i < 64; ++i) {
        float4 v = *(const float4*)(train + (size_t)(rbase + i * 4) * D + c4);
        s[0] += v.x; s2[0] += (double)v.x * v.x;
        s[1] += v.y; s2[1] += (double)v.y * v.y;
        s[2] += v.z; s2[2] += (double)v.z * v.z;
        s[3] += v.w; s2[3] += (double)v.w * v.w;
    }
    __shared__ double sh[2][4][D];
#pragma unroll
    for (int j = 0; j < 4; ++j) { sh[0][warp][c4 + j] = s[j]; sh[1][warp][c4 + j] = s2[j]; }
    __syncthreads();
    const int c = threadIdx.x;
    double a = 0, b2 = 0;
#pragma unroll
    for (int w = 0; w < 4; ++w) { a += sh[0][w][c]; b2 += sh[1][w][c]; }
    atomicAdd(&g_colsum[c], a);
    atomicAdd(&g_colsumsq[c], b2);
}

// -------- launch 2: bandwidth + Z; re-arm state for next replay --------
__global__ void k_finalize(float* __restrict__ out) {
    int c = threadIdx.x;
    const double n = (double)NTRAIN;
    double mean = g_colsum[c] / n;
    double var  = (g_colsumsq[c] - n * mean * mean) / (n - 1.0);
    double sd   = sqrt(fmax(var, 0.0));
    sd = fmax(sd, 0.01);
    double bw = 1.06 * sd * exp(-log(n) / (4.0 + (double)D));
    bw = fmin(bw, 0.49);
    g_inv_bw[c] = (float)(1.0 / bw);

    __shared__ double red[D];
    red[c] = log(bw);
    __syncthreads();
    for (int off = 64; off; off >>= 1) {
        if (c < off) red[c] += red[c + off];
        __syncthreads();
    }
    if (c == 0) {
        double Z = 0.5 * (double)D * log(2.0 * 3.14159265358979323846) + red[0] + log(n);
        g_Z = (float)Z;
    }
    g_colsum[c] = 0.0;
    g_colsumsq[c] = 0.0;
    for (int i = c; i < NTEST; i += 128) out[i] = 0.f;
}

// -------- launch 3: scale, fp16 two-limb split, norms (warp-per-row, float4) --------
__global__ void k_split(const float* __restrict__ test, const float* __restrict__ train) {
    const int lane = threadIdx.x & 31;
    const int r = blockIdx.x * 8 + (threadIdx.x >> 5);
    const float* src; __half *d1, *d2; float* nrm; int rr = r;
    if (r < NTEST) { src = test;  d1 = g_Ah1; d2 = g_Ah2; nrm = g_tnorm; }
    else { rr = r - NTEST; src = train; d1 = g_Bh1; d2 = g_Bh2; nrm = g_trnorm; }

    const int c4 = lane * 4;
    float4 v = *(const float4*)(src + (size_t)rr * D + c4);
    float4 w = *(const float4*)(g_inv_bw + c4);
    v.x *= w.x; v.y *= w.y; v.z *= w.z; v.w *= w.w;

    __half2 p1a = __floats2half2_rn(v.x, v.y);
    __half2 p1b = __floats2half2_rn(v.z, v.w);
    float2 f1a = __half22float2(p1a), f1b = __half22float2(p1b);
    __half2 p2a = __floats2half2_rn(v.x - f1a.x, v.y - f1a.y);
    __half2 p2b = __floats2half2_rn(v.z - f1b.x, v.w - f1b.y);

    *(__half2*)(d1 + (size_t)rr * D + c4)     = p1a;
    *(__half2*)(d1 + (size_t)rr * D + c4 + 2) = p1b;
    *(__half2*)(d2 + (size_t)rr * D + c4)     = p2a;
    *(__half2*)(d2 + (size_t)rr * D + c4 + 2) = p2b;

    float s = v.x * v.x + v.y * v.y + v.z * v.z + v.w * v.w;
#pragma unroll
    for (int off = 16; off; off >>= 1) s += __shfl_xor_sync(0xffffffffu, s, off);
    if (lane == 0) nrm[rr] = s;
}

// -------- launch 4: persistent HMMA split-fp16 GEMM + fused KDE epilogue --------
// 2 blocks/SM; co-resident blocks overlap epilogue (MUFU/FMA) with MMA.
extern __shared__ char smem[];

__global__ void __launch_bounds__(NTHREADS, 2) k_main(float* __restrict__ out) {
    const uint32_t sb = smem_u32(smem);
    const int tid = threadIdx.x, lane = tid & 31, wid = tid >> 5;
    const int wm = wid & 3, wn = wid >> 2;   // warp tile: rows wm*32, cols wn*32
    const int qr = lane >> 2, qc = lane & 3;

    const int G = gridDim.x, b = blockIdx.x;
    const int per = NJOBS / G, rem = NJOBS % G;
    const int lo = b * per + min(b, rem);
    const int nloc = per + (b < rem ? 1 : 0);
    if (nloc <= 0) return;

    const float Zf = g_Z;
    const float c0v = -0.72134752f / Zf;  // -0.5*log2(e)/Z
    const float c1v = -1.44269504f;       // -log2(e)

    int rowid[4];
#pragma unroll
    for (int i = 0; i < 4; ++i) rowid[i] = wm * 32 + (i >> 1) * 16 + (i & 1) * 8 + qr;

    const int arow = wm * 32 + (lane & 15);
    const int akg  = lane >> 4;
    const int nofs = (lane & 7) + ((lane >> 4) << 3);
    const int bkg  = (lane >> 3) & 1;

    auto loadA = [&](int mbase) {
        for (int i = tid; i < 4096; i += NTHREADS) {
            int l = i >> 11, idx = i & 2047;
            int r = idx >> 4, g = idx & 15;
            const __half* src = (l ? g_Ah2 : g_Ah1) + (size_t)(mbase + r) * D + g * 8;
            cp16s(sb + SM_A + l * 32768 + (uint32_t)(r * 256 + ((g ^ (r & 7)) << 4)), src);
        }
        asm volatile("cp.async.commit_group;" ::: "memory");
        asm volatile("cp.async.wait_all;" ::: "memory");
        __syncthreads();
    };
    // single-buffered B (32KB: 64 rows x 2 limbs); trn double-buffered
    auto loadB = [&](int nt, int tbuf) {
        int nbase = nt * TN;
        for (int i = tid; i < 2048; i += NTHREADS) {
            int l = i >> 10, idx = i & 1023;
            int r = idx >> 4, g = idx & 15;
            const __half* src = (l ? g_Bh2 : g_Bh1) + (size_t)(nbase + r) * D + g * 8;
            cp16s(sb + SM_B + l * 16384 + (uint32_t)(r * 256 + ((g ^ (r & 7)) << 4)), src);
        }
        if (tid < 16)
            cp16s(sb + SM_TRN + tbuf * 256 + tid * 16, g_trnorm + nbase + tid * 4);
        asm volatile("cp.async.commit_group;" ::: "memory");
    };

    float acc[2][4][4];
    float accR[4] = {0.f, 0.f, 0.f, 0.f};
    float tnr[4];

    int cur_m = lo >> 8;   // / NTILES
    loadA(cur_m * TM);
    loadB(lo & (NTILES - 1), 0);
#pragma unroll
    for (int i = 0; i < 4; ++i) tnr[i] = g_tnorm[cur_m * TM + rowid[i]];

    for (int t = 0; t < nloc; ++t) {
        const int job = lo + t;
        const int mt = job >> 8;

        if (mt != cur_m) {
            if (qc == 0) {
#pragma unroll
                for (int i = 0; i < 4; ++i) {
                    atomicAdd(&out[cur_m * TM + rowid[i]], accR[i]);
                    accR[i] = 0.f;
                }
            } else {
#pragma unroll
                for (int i = 0; i < 4; ++i) accR[i] = 0.f;
            }
            __syncthreads();
            loadA(mt * TM);   // wait_all inside also drains pending B prefetch
            cur_m = mt;
#pragma unroll
            for (int i = 0; i < 4; ++i) tnr[i] = g_tnorm[cur_m * TM + rowid[i]];
        }

        asm volatile("cp.async.wait_group 0;" ::: "memory");
        __syncthreads();   // B(t) + trn(t) ready

#pragma unroll
        for (int im = 0; im < 2; ++im)
#pragma unroll
            for (int jn = 0; jn < 4; ++jn)
#pragma unroll
                for (int e = 0; e < 4; ++e) acc[im][jn][e] = 0.f;

        const uint32_t A0 = sb + SM_A, A1 = A0 + 32768;
        const uint32_t B0 = sb + SM_B, B1 = B0 + 16384;

        // fused 3-limb mainloop: acc += A0*B0 + A0*B1 + A1*B0
#pragma unroll
        for (int ks = 0; ks < 8; ++ks) {
            const int ga = ks * 2 + akg, gb = ks * 2 + bkg;
            uint32_t a0[2][4], a1[2][4];
#pragma unroll
            for (int im = 0; im < 2; ++im) {
                int row = arow + im * 16;
                uint32_t off = (uint32_t)(row * 256 + ((ga ^ (row & 7)) << 4));
                ldsm_x4(a0[im], A0 + off);
                ldsm_x4(a1[im], A1 + off);
            }
            uint32_t b0f[2][4], b1f[2][4];
#pragma unroll
            for (int j = 0; j < 2; ++j) {
                int row = wn * 32 + j * 16 + nofs;
                uint32_t off = (uint32_t)(row * 256 + ((gb ^ (row & 7)) << 4));
                ldsm_x4(b0f[j], B0 + off);
                ldsm_x4(b1f[j], B1 + off);
            }
#pragma unroll
            for (int im = 0; im < 2; ++im)
#pragma unroll
                for (int jn = 0; jn < 4; ++jn) {
                    uint32_t lo0 = b0f[jn >> 1][(jn & 1) * 2], hi0 = b0f[jn >> 1][(jn & 1) * 2 + 1];
                    uint32_t lo1 = b1f[jn >> 1][(jn & 1) * 2], hi1 = b1f[jn >> 1][(jn & 1) * 2 + 1];
                    mma16816(acc[im][jn], a0[im], lo0, hi0);
                    mma16816(acc[im][jn], a0[im], lo1, hi1);
                    mma16816(acc[im][jn], a1[im], lo0, hi0);
                }
        }

        __syncthreads();   // all warps done reading B(t)
        if (t + 1 < nloc) loadB((job + 1) & (NTILES - 1), (t + 1) & 1);  // overlaps epilogue

        // fused epilogue (acc regs + trn buf t&1)
        const float* trn = (const float*)(smem + SM_TRN + (t & 1) * 256);
#pragma unroll
        for (int im = 0; im < 2; ++im)
#pragma unroll
            for (int h = 0; h < 2; ++h) {
                float s = 0.f;
                const float tv = tnr[im * 2 + h];
#pragma unroll
                for (int jn = 0; jn < 4; ++jn) {
                    int n0 = wn * 32 + jn * 8 + qc * 2;
                    float d0 = acc[im][jn][2 * h], d1 = acc[im][jn][2 * h + 1];
                    float s0 = fmaxf(fmaf(-2.f, d0, tv + trn[n0]), 0.f);
                    float s1 = fmaxf(fmaf(-2.f, d1, tv + trn[n0 + 1]), 0.f);
                    s += ex2(fmaf(s0, c0v, c1v));
                    s += ex2(fmaf(s1, c0v, c1v));
                }
                s += __shfl_xor_sync(0xffffffffu, s, 1);
                s += __shfl_xor_sync(0xffffffffu, s, 2);
                if (qc == 0) accR[im * 2 + h] += s;
            }
    }

    if (qc == 0) {
#pragma unroll
        for (int i = 0; i < 4; ++i)
            atomicAdd(&out[cur_m * TM + rowid[i]], accR[i]);
    }
}

extern "C" void kernel_launch(void* const* d_in, const int* in_sizes, int n_in,
                              void* d_out, int out_size) {
    const float* test  = (const float*)d_in[0];
    const float* train = (const float*)d_in[1];
    float* out = (float*)d_out;
    (void)in_sizes; (void)n_in; (void)out_size;

    int dev = 0;
    cudaGetDevice(&dev);
    int smc = 148;
    cudaDeviceGetAttribute(&smc, cudaDevAttrMultiProcessorCount, dev);

    cudaFuncSetAttribute(k_main, cudaFuncAttributeMaxDynamicSharedMemorySize, SM_TOTAL);

    k_colstats<<<64, 128>>>(train);
    k_finalize<<<1, 128>>>(out);
    k_split<<<(NTEST + NTRAIN) / 8, 256>>>(test, train);
    k_main<<<2 * smc, NTHREADS, SM_TOTAL>>>(out);
}

// round 8
// speedup vs baseline: 2.0506x; 1.0022x over previous
#include <cuda_runtime.h>
#include <cuda_fp16.h>
#include <cstdint>

#define D        128
#define NTEST    4096
#define NTRAIN   16384
#define TM       128
#define TN       64
#define NTILES   256                // n-chunks per m-tile
#define NJOBS    (32 * NTILES)      // 8192
#define NTHREADS 512                // 8 MMA warps + 8 epilogue warps

// ---------------- device scratch (zero-initialized at module load) ----------------
__device__ double g_colsum[D];
__device__ double g_colsumsq[D];
__device__ float  g_inv_bw[D];
__device__ float  g_Z;
__device__ __half g_Ah1[NTEST * D];
__device__ __half g_Ah2[NTEST * D];
__device__ __half g_Bh1[NTRAIN * D];
__device__ __half g_Bh2[NTRAIN * D];
__device__ float  g_tnorm[NTEST];
__device__ float  g_trnorm[NTRAIN];

// ---------------- helpers ----------------
__device__ __forceinline__ uint32_t smem_u32(const void* p) {
    uint32_t a;
    asm("{ .reg .u64 t; cvta.to.shared.u64 t, %1; cvt.u32.u64 %0, t; }" : "=r"(a) : "l"(p));
    return a;
}
__device__ __forceinline__ void cp16s(uint32_t dst, const void* src) {
    asm volatile("cp.async.cg.shared.global [%0], [%1], 16;" :: "r"(dst), "l"(src));
}
__device__ __forceinline__ float ex2(float x) {
    float r; asm("ex2.approx.ftz.f32 %0, %1;" : "=f"(r) : "f"(x)); return r;
}
__device__ __forceinline__ void ldsm_x4(uint32_t (&r)[4], uint32_t addr) {
    asm volatile("ldmatrix.sync.aligned.m8n8.x4.shared.b16 {%0,%1,%2,%3}, [%4];"
                 : "=r"(r[0]), "=r"(r[1]), "=r"(r[2]), "=r"(r[3]) : "r"(addr));
}
__device__ __forceinline__ void mma16816(float (&d)[4], const uint32_t (&a)[4],
                                         uint32_t b0, uint32_t b1) {
    asm volatile("mma.sync.aligned.m16n8k16.row.col.f32.f16.f16.f32 "
                 "{%0,%1,%2,%3}, {%4,%5,%6,%7}, {%8,%9}, {%0,%1,%2,%3};"
                 : "+f"(d[0]), "+f"(d[1]), "+f"(d[2]), "+f"(d[3])
                 : "r"(a[0]), "r"(a[1]), "r"(a[2]), "r"(a[3]), "r"(b0), "r"(b1));
}
__device__ __forceinline__ void barw(int id) {   // blocking sync (counts as arrival)
    asm volatile("bar.sync %0, 512;" :: "r"(id) : "memory");
}
__device__ __forceinline__ void bara(int id) {   // non-blocking arrive
    asm volatile("bar.arrive %0, 512;" :: "r"(id) : "memory");
}
__device__ __forceinline__ void sts_v2(uint32_t addr, float x, float y) {
    asm volatile("st.shared.v2.f32 [%0], {%1, %2};" :: "r"(addr), "f"(x), "f"(y) : "memory");
}

// ---------------- SMEM layout (bytes) ----------------
// A:   [0, 65536)        limb0 32K | limb1 32K   ([m][k], 16B-group XOR swizzle)
// B:   [65536, 131072)   2 bufs x 32K (limb0 16K | limb1 16K)
// ACC: [131072, 204800)  2 bufs x 36864 (128 rows x 72 floats, padded stride)
// TRN: [204800, 205312)  2 x 256
#define SM_A      0
#define SM_B      65536
#define SM_ACC    131072
#define SM_TRN    204800
#define SM_TOTAL  205312
#define ACC_STRIDE 72

// barrier ids: 1,2=Bfull[buf]  3,4=Bfree[buf]  5,6=ACCfull[buf]  7,8=ACCfree[buf]
// 9 = compute-group-only (count 256) for A reload

// -------- launch 1: per-column sum / sumsq over train --------
__global__ void k_colstats(const float* __restrict__ train) {
    const int warp = threadIdx.x >> 5, lane = threadIdx.x & 31;
    const int c4 = lane * 4;
    double s[4] = {0, 0, 0, 0}, s2[4] = {0, 0, 0, 0};
    const int rbase = blockIdx.x * 128 + warp;
#pragma unroll 4
    for (int i = 0; i < 16; ++i) {
        float4 v = *(const float4*)(train + (size_t)(rbase + i * 8) * D + c4);
        s[0] += v.x; s2[0] += (double)v.x * v.x;
        s[1] += v.y; s2[1] += (double)v.y * v.y;
        s[2] += v.z; s2[2] += (double)v.z * v.z;
        s[3] += v.w; s2[3] += (double)v.w * v.w;
    }
    __shared__ double sh[2][8][D];
#pragma unroll
    for (int j = 0; j < 4; ++j) { sh[0][warp][c4 + j] = s[j]; sh[1][warp][c4 + j] = s2[j]; }
    __syncthreads();
    if (threadIdx.x < D) {
        const int c = threadIdx.x;
        double a = 0, b2 = 0;
#pragma unroll
        for (int w = 0; w < 8; ++w) { a += sh[0][w][c]; b2 += sh[1][w][c]; }
        atomicAdd(&g_colsum[c], a);
        atomicAdd(&g_colsumsq[c], b2);
    }
}

// -------- launch 2: bandwidth + Z; re-arm state; zero out --------
__global__ void k_finalize(float* __restrict__ out) {
    int c = threadIdx.x;
    const double n = (double)NTRAIN;
    double mean = g_colsum[c] / n;
    double var  = (g_colsumsq[c] - n * mean * mean) / (n - 1.0);
    double sd   = sqrt(fmax(var, 0.0));
    sd = fmax(sd, 0.01);
    double bw = 1.06 * sd * exp(-log(n) / (4.0 + (double)D));
    bw = fmin(bw, 0.49);
    g_inv_bw[c] = (float)(1.0 / bw);

    __shared__ double red[D];
    red[c] = log(bw);
    __syncthreads();
    for (int off = 64; off; off >>= 1) {
        if (c < off) red[c] += red[c + off];
        __syncthreads();
    }
    if (c == 0) {
        double Z = 0.5 * (double)D * log(2.0 * 3.14159265358979323846) + red[0] + log(n);
        g_Z = (float)Z;
    }
    g_colsum[c] = 0.0;
    g_colsumsq[c] = 0.0;
    for (int i = c; i < NTEST; i += 128) out[i] = 0.f;
}

// -------- launch 3: scale, fp16 two-limb split, norms --------
__global__ void k_split(const float* __restrict__ test, const float* __restrict__ train) {
    const int lane = threadIdx.x & 31;
    const int r = blockIdx.x * 8 + (threadIdx.x >> 5);
    const float* src; __half *d1, *d2; float* nrm; int rr = r;
    if (r < NTEST) { src = test;  d1 = g_Ah1; d2 = g_Ah2; nrm = g_tnorm; }
    else { rr = r - NTEST; src = train; d1 = g_Bh1; d2 = g_Bh2; nrm = g_trnorm; }

    const int c4 = lane * 4;
    float4 v = *(const float4*)(src + (size_t)rr * D + c4);
    float4 w = *(const float4*)(g_inv_bw + c4);
    v.x *= w.x; v.y *= w.y; v.z *= w.z; v.w *= w.w;

    __half2 p1a = __floats2half2_rn(v.x, v.y);
    __half2 p1b = __floats2half2_rn(v.z, v.w);
    float2 f1a = __half22float2(p1a), f1b = __half22float2(p1b);
    __half2 p2a = __floats2half2_rn(v.x - f1a.x, v.y - f1a.y);
    __half2 p2b = __floats2half2_rn(v.z - f1b.x, v.w - f1b.y);

    *(__half2*)(d1 + (size_t)rr * D + c4)     = p1a;
    *(__half2*)(d1 + (size_t)rr * D + c4 + 2) = p1b;
    *(__half2*)(d2 + (size_t)rr * D + c4)     = p2a;
    *(__half2*)(d2 + (size_t)rr * D + c4 + 2) = p2b;

    float s = v.x * v.x + v.y * v.y + v.z * v.z + v.w * v.w;
#pragma unroll
    for (int off = 16; off; off >>= 1) s += __shfl_xor_sync(0xffffffffu, s, off);
    if (lane == 0) nrm[rr] = s;
}

// -------- launch 4: warp-specialized HMMA GEMM + decoupled KDE epilogue --------
extern __shared__ char smem[];

__global__ void __launch_bounds__(NTHREADS, 1) k_main(float* __restrict__ out) {
    const uint32_t sb = smem_u32(smem);
    const int tid = threadIdx.x, lane = tid & 31, wid = tid >> 5;

    const int G = gridDim.x, b = blockIdx.x;
    const int per = NJOBS / G, rem = NJOBS % G;
    const int lo = b * per + min(b, rem);
    const int nloc = per + (b < rem ? 1 : 0);
    if (nloc <= 0) return;

    if (wid < 8) {
        // ================= MMA warps (threads 0..255) =================
        const int wm = wid & 3, wn = wid >> 2;
        const int qr = lane >> 2, qc = lane & 3;
        const int arow = wm * 32 + (lane & 15);
        const int akg  = lane >> 4;
        const int nofs = (lane & 7) + ((lane >> 4) << 3);
        const int bkg  = (lane >> 3) & 1;

        float acc[2][4][4];
        int cur_m = -1;

        for (int t = 0; t < nloc; ++t) {
            const int job = lo + t;
            const int mt = job >> 8;
            const int buf = t & 1;

            if (mt != cur_m) {
                const int mbase = mt * TM;
                for (int i = tid; i < 4096; i += 256) {
                    int l = i >> 11, idx = i & 2047;
                    int r = idx >> 4, g = idx & 15;
                    const __half* src = (l ? g_Ah2 : g_Ah1) + (size_t)(mbase + r) * D + g * 8;
                    cp16s(sb + SM_A + l * 32768 + (uint32_t)(r * 256 + ((g ^ (r & 7)) << 4)), src);
                }
                asm volatile("cp.async.commit_group;" ::: "memory");
                asm volatile("cp.async.wait_all;" ::: "memory");
                asm volatile("bar.sync 9, 256;" ::: "memory");
                cur_m = mt;
            }

            barw(1 + buf);                 // wait B(t) + trn(t) ready

#pragma unroll
            for (int im = 0; im < 2; ++im)
#pragma unroll
                for (int jn = 0; jn < 4; ++jn)
#pragma unroll
                    for (int e = 0; e < 4; ++e) acc[im][jn][e] = 0.f;

            const uint32_t A0 = sb + SM_A, A1 = A0 + 32768;
            const uint32_t B0 = sb + SM_B + buf * 32768, B1 = B0 + 16384;

#pragma unroll
            for (int ks = 0; ks < 8; ++ks) {
                const int ga = ks * 2 + akg, gb = ks * 2 + bkg;
                uint32_t a0[2][4], a1[2][4];
#pragma unroll
                for (int im = 0; im < 2; ++im) {
                    int row = arow + im * 16;
                    uint32_t off = (uint32_t)(row * 256 + ((ga ^ (row & 7)) << 4));
                    ldsm_x4(a0[im], A0 + off);
                    ldsm_x4(a1[im], A1 + off);
                }
                uint32_t b0f[2][4], b1f[2][4];
#pragma unroll
                for (int j = 0; j < 2; ++j) {
                    int row = wn * 32 + j * 16 + nofs;
                    uint32_t off = (uint32_t)(row * 256 + ((gb ^ (row & 7)) << 4));
                    ldsm_x4(b0f[j], B0 + off);
                    ldsm_x4(b1f[j], B1 + off);
                }
#pragma unroll
                for (int im = 0; im < 2; ++im)
#pragma unroll
                    for (int jn = 0; jn < 4; ++jn) {
                        uint32_t l0 = b0f[jn >> 1][(jn & 1) * 2], h0 = b0f[jn >> 1][(jn & 1) * 2 + 1];
                        uint32_t l1 = b1f[jn >> 1][(jn & 1) * 2], h1 = b1f[jn >> 1][(jn & 1) * 2 + 1];
                        mma16816(acc[im][jn], a0[im], l0, h0);
                        mma16816(acc[im][jn], a0[im], l1, h1);
                        mma16816(acc[im][jn], a1[im], l0, h0);
                    }
            }

            bara(3 + buf);                 // B(t) consumed
            if (t >= 2) barw(7 + buf);     // wait acc buf free

            // STS acc tile to canonical [row][col] layout (stride 72 floats)
            const uint32_t ab = sb + SM_ACC + buf * 36864;
#pragma unroll
            for (int im = 0; im < 2; ++im)
#pragma unroll
                for (int jn = 0; jn < 4; ++jn)
#pragma unroll
                    for (int h = 0; h < 2; ++h) {
                        int r = wm * 32 + im * 16 + h * 8 + qr;
                        int c = wn * 32 + jn * 8 + qc * 2;
                        sts_v2(ab + (uint32_t)(r * ACC_STRIDE + c) * 4,
                               acc[im][jn][2 * h], acc[im][jn][2 * h + 1]);
                    }
            bara(5 + buf);                 // acc(t) published
        }
    } else {
        // ================= epilogue warps (threads 256..511) =================
        const int et = tid - 256;
        const int row = et & 127, ch = et >> 7;

        const float Zf = g_Z;
        const float c0v = -0.72134752f / Zf;  // -0.5*log2(e)/Z
        const float c1v = -1.44269504f;       // -log2(e)

        auto loadB = [&](int jobidx, int buf) {
            const int nbase = (jobidx & (NTILES - 1)) * TN;
            for (int i = et; i < 2048; i += 256) {
                int l = i >> 10, idx = i & 1023;
                int r = idx >> 4, g = idx & 15;
                const __half* src = (l ? g_Bh2 : g_Bh1) + (size_t)(nbase + r) * D + g * 8;
                cp16s(sb + SM_B + buf * 32768 + l * 16384 +
                          (uint32_t)(r * 256 + ((g ^ (r & 7)) << 4)), src);
            }
            if (et < 16)
                cp16s(sb + SM_TRN + buf * 256 + et * 16, g_trnorm + nbase + et * 4);
            asm volatile("cp.async.commit_group;" ::: "memory");
        };

        // prologue: B(0) -> buf0 (waited), B(1) -> buf1 (in flight)
        loadB(lo, 0);
        asm volatile("cp.async.wait_group 0;" ::: "memory");
        bara(1);                           // Bfull0
        if (nloc > 1) loadB(lo + 1, 1);

        float accR = 0.f, tn = 0.f;
        int cur_m = -1;

        for (int t = 0; t < nloc; ++t) {
            const int job = lo + t;
            const int buf = t & 1;

            if (t + 1 < nloc) {            // signal B(t+1) ready ASAP
                asm volatile("cp.async.wait_group 0;" ::: "memory");
                bara(1 + ((t + 1) & 1));
            }

            const int mt = job >> 8;
            if (mt != cur_m) {
                if (cur_m >= 0) { atomicAdd(&out[cur_m * TM + row], accR); accR = 0.f; }
                cur_m = mt;
                tn = g_tnorm[mt * TM + row];
            }

            barw(5 + buf);                 // wait acc(t)
            const float* accs = (const float*)(smem + SM_ACC + buf * 36864)
                                + row * ACC_STRIDE + ch * 32;
            const float* trn = (const float*)(smem + SM_TRN + buf * 256) + ch * 32;
            float s = 0.f;
#pragma unroll
            for (int j = 0; j < 32; j += 4) {
                float4 dv = *(const float4*)(accs + j);
                float s0 = fmaxf(fmaf(-2.f, dv.x, tn + trn[j]),     0.f);
                float s1 = fmaxf(fmaf(-2.f, dv.y, tn + trn[j + 1]), 0.f);
                float s2 = fmaxf(fmaf(-2.f, dv.z, tn + trn[j + 2]), 0.f);
                float s3 = fmaxf(fmaf(-2.f, dv.w, tn + trn[j + 3]), 0.f);
                s += ex2(fmaf(s0, c0v, c1v));
                s += ex2(fmaf(s1, c0v, c1v));
                s += ex2(fmaf(s2, c0v, c1v));
                s += ex2(fmaf(s3, c0v, c1v));
            }
            accR += s;
            bara(7 + buf);                 // acc buf free

            if (t + 2 < nloc) {
                barw(3 + buf);             // B buf free (compute done with B(t))
                loadB(lo + t + 2, buf);
            }
        }
        atomicAdd(&out[cur_m * TM + row], accR);
    }
}

extern "C" void kernel_launch(void* const* d_in, const int* in_sizes, int n_in,
                              void* d_out, int out_size) {
    const float* test  = (const float*)d_in[0];
    const float* train = (const float*)d_in[1];
    float* out = (float*)d_out;
    (void)in_sizes; (void)n_in; (void)out_size;

    int dev = 0;
    cudaGetDevice(&dev);
    int smc = 148;
    cudaDeviceGetAttribute(&smc, cudaDevAttrMultiProcessorCount, dev);

    cudaFuncSetAttribute(k_main, cudaFuncAttributeMaxDynamicSharedMemorySize, SM_TOTAL);

    k_colstats<<<128, 256>>>(train);
    k_finalize<<<1, 128>>>(out);
    k_split<<<(NTEST + NTRAIN) / 8, 256>>>(test, train);
    k_main<<<smc, NTHREADS, SM_TOTAL>>>(out);
}